// round 6
// baseline (speedup 1.0000x reference)
#include <cuda_runtime.h>

// Problem constants
#define B_  64
#define H_  1024
#define I_  1024
#define BH  (B_ * H_)          // 65536
#define BHI ((size_t)BH * I_)  // 67108864
#define ROWS 8                 // (b,h) rows per block; consecutive bh share b

// ---------------------------------------------------------------------------
// Fused kernel, 8 rows per 256-thread block, two phases:
//   Phase 1 (L2-hot): gate GEMV partials for 8 rows vs one x chunk,
//                     block reduction, parallel epilogue (threads 0..7).
//   Phase 2 (DRAM):   stream Z/F rows: load -> FMA -> store per row, so no
//                     wide register arrays live across the barriers.
// ---------------------------------------------------------------------------
__global__ void __launch_bounds__(256) fused_kernel(
    const float4* __restrict__ x4,     // [B, I/4]
    const float*  __restrict__ hidden_prev,
    const float4* __restrict__ Z,      // [BH, I/4]
    const float4* __restrict__ F,
    const float*  __restrict__ wz_state,
    const float*  __restrict__ wf_state,
    const float*  __restrict__ bz_state,
    const float*  __restrict__ bf_state,
    const float4* __restrict__ wmz4,   // [H, I/4]
    const float4* __restrict__ wmf4,
    const float*  __restrict__ wv_z,   // [H]
    const float*  __restrict__ wv_f,
    const float*  __restrict__ bias_z,
    const float*  __restrict__ bias_f,
    float*  __restrict__ out_cell,     // [B, H]
    float4* __restrict__ Zo,
    float4* __restrict__ Fo,
    float*  __restrict__ out_wz,
    float*  __restrict__ out_wf,
    float*  __restrict__ out_bz,
    float*  __restrict__ out_bf)
{
    __shared__ float red[8][2 * ROWS];   // [warp][r*2 + gate]
    __shared__ float coef[3][ROWS];

    const int bh0  = blockIdx.x * ROWS;
    const int b    = bh0 >> 10;
    const int h0   = bh0 & (H_ - 1);
    const int t    = threadIdx.x;
    const int wid  = t >> 5;
    const int lane = t & 31;

    const size_t row0 = (size_t)bh0 << 8;   // float4 offset of first row

    // ---- epilogue scalar preloads: threads 0..7, one row each ----
    float hp = 0.f, wzs = 0.f, wfs = 0.f, bzs = 0.f, bfs = 0.f;
    float vz = 0.f, vf = 0.f, bsz = 0.f, bsf = 0.f;
    if (t < ROWS) {
        const int bh = bh0 + t;
        const int h  = h0 + t;
        hp  = hidden_prev[bh];
        wzs = wz_state[bh];  wfs = wf_state[bh];
        bzs = bz_state[bh];  bfs = bf_state[bh];
        vz  = wv_z[h];       vf  = wv_f[h];
        bsz = bias_z[h];     bsf = bias_f[h];
    }

    // ---- phase 1: GEMV partials (x + wm rows, L2-hot) ----
    const float4 xv = __ldg(x4 + ((size_t)b << 8) + t);
    float pz[ROWS], pf[ROWS];
    #pragma unroll
    for (int r = 0; r < ROWS; ++r) {
        const float4 wzv = __ldg(wmz4 + ((size_t)(h0 + r) << 8) + t);
        const float4 wfv = __ldg(wmf4 + ((size_t)(h0 + r) << 8) + t);
        pz[r] = xv.x * wzv.x + xv.y * wzv.y + xv.z * wzv.z + xv.w * wzv.w;
        pf[r] = xv.x * wfv.x + xv.y * wfv.y + xv.z * wfv.z + xv.w * wfv.w;
    }
    #pragma unroll
    for (int o = 16; o > 0; o >>= 1) {
        #pragma unroll
        for (int r = 0; r < ROWS; ++r) {
            pz[r] += __shfl_xor_sync(0xffffffffu, pz[r], o);
            pf[r] += __shfl_xor_sync(0xffffffffu, pf[r], o);
        }
    }
    if (lane == 0) {
        #pragma unroll
        for (int r = 0; r < ROWS; ++r) {
            red[wid][r * 2]     = pz[r];
            red[wid][r * 2 + 1] = pf[r];
        }
    }
    __syncthreads();

    // ---- epilogue: threads 0..7 in parallel, operands already in regs ----
    if (t < ROWS) {
        float AZ = 0.f, AF = 0.f;
        #pragma unroll
        for (int w = 0; w < 8; ++w) {
            AZ += red[w][t * 2];
            AF += red[w][t * 2 + 1];
        }

        const int bh = bh0 + t;
        const float z    = tanhf(AZ + vz * hp + bsz);
        const float fpre = AF + vf * hp + bsf;
        const float f    = 1.f / (1.f + expf(-fpre));

        const float zf = (1.f - f) * (1.f - z * z);
        const float fz = (hp - z) * (1.f - f) * f;
        const float common = f + zf * vz + fz * vf;

        out_cell[bh] = hp * f + (1.f - f) * z;
        out_wz[bh]   = hp * zf + common * wzs;
        out_wf[bh]   = hp * fz + common * wfs;
        out_bz[bh]   = zf + common * bzs;
        out_bf[bh]   = fz + common * bfs;

        coef[0][t] = common;
        coef[1][t] = zf;
        coef[2][t] = fz;
    }
    __syncthreads();

    // ---- phase 2: stream Z/F rows (touch-once): load -> FMA -> store ----
    #pragma unroll
    for (int r = 0; r < ROWS; ++r) {
        const size_t off = row0 + (size_t)(r << 8) + t;
        const float4 zv = __ldcs(Z + off);
        const float4 fv = __ldcs(F + off);

        const float c   = coef[0][r];
        const float czf = coef[1][r];
        const float cfz = coef[2][r];

        float4 zo, fo;
        zo.x = c * zv.x + czf * xv.x;
        zo.y = c * zv.y + czf * xv.y;
        zo.z = c * zv.z + czf * xv.z;
        zo.w = c * zv.w + czf * xv.w;
        fo.x = c * fv.x + cfz * xv.x;
        fo.y = c * fv.y + cfz * xv.y;
        fo.z = c * fv.z + cfz * xv.z;
        fo.w = c * fv.w + cfz * xv.w;

        __stcs(Zo + off, zo);
        __stcs(Fo + off, fo);
    }
}

// ---------------------------------------------------------------------------
extern "C" void kernel_launch(void* const* d_in, const int* in_sizes, int n_in,
                              void* d_out, int out_size)
{
    const float* x           = (const float*)d_in[0];
    const float* hidden_prev = (const float*)d_in[1];
    const float* Z_state     = (const float*)d_in[2];
    const float* F_state     = (const float*)d_in[3];
    const float* wz_state    = (const float*)d_in[4];
    const float* wf_state    = (const float*)d_in[5];
    const float* bz_state    = (const float*)d_in[6];
    const float* bf_state    = (const float*)d_in[7];
    const float* wm_z        = (const float*)d_in[8];
    const float* wm_f        = (const float*)d_in[9];
    const float* wv_z        = (const float*)d_in[10];
    const float* wv_f        = (const float*)d_in[11];
    const float* bias_z      = (const float*)d_in[12];
    const float* bias_f      = (const float*)d_in[13];

    float* out = (float*)d_out;
    // Output tuple layout: new_cell, Z_new, F_new, wz_new, wf_new, bz_new, bf_new
    float* o_cell = out;
    float* o_Z    = out + BH;
    float* o_F    = o_Z + BHI;
    float* o_wz   = o_F + BHI;
    float* o_wf   = o_wz + BH;
    float* o_bz   = o_wf + BH;
    float* o_bf   = o_bz + BH;

    fused_kernel<<<BH / ROWS, 256>>>(
        (const float4*)x, hidden_prev,
        (const float4*)Z_state, (const float4*)F_state,
        wz_state, wf_state, bz_state, bf_state,
        (const float4*)wm_z, (const float4*)wm_f,
        wv_z, wv_f, bias_z, bias_f,
        o_cell, (float4*)o_Z, (float4*)o_F,
        o_wz, o_wf, o_bz, o_bf);
}

// round 7
// speedup vs baseline: 1.0767x; 1.0767x over previous
#include <cuda_runtime.h>

// Problem constants
#define B_  64
#define H_  1024
#define I_  1024
#define BH  (B_ * H_)          // 65536
#define BHI ((size_t)BH * I_)  // 67108864
#define ROWS 8                 // (b,h) rows per block; consecutive bh share b

// ---------------------------------------------------------------------------
// Fused kernel, 8 rows per 256-thread block, software-pipelined stream:
//   - prefetch stream rows 0..1 BEFORE the GEMV/reduction (latency overlaps
//     the serial reduction + epilogue chain)
//   - phase 1 (L2-hot): gate GEMV partials for 8 rows, block reduction,
//     parallel epilogue (threads 0..7, scalars preloaded)
//   - phase 2: compute/store row r while prefetching row r+2 (2-deep pipe,
//     >= 8 KB/warp of DRAM traffic always in flight)
// ---------------------------------------------------------------------------
__global__ void __launch_bounds__(256) fused_kernel(
    const float4* __restrict__ x4,     // [B, I/4]
    const float*  __restrict__ hidden_prev,
    const float4* __restrict__ Z,      // [BH, I/4]
    const float4* __restrict__ F,
    const float*  __restrict__ wz_state,
    const float*  __restrict__ wf_state,
    const float*  __restrict__ bz_state,
    const float*  __restrict__ bf_state,
    const float4* __restrict__ wmz4,   // [H, I/4]
    const float4* __restrict__ wmf4,
    const float*  __restrict__ wv_z,   // [H]
    const float*  __restrict__ wv_f,
    const float*  __restrict__ bias_z,
    const float*  __restrict__ bias_f,
    float*  __restrict__ out_cell,     // [B, H]
    float4* __restrict__ Zo,
    float4* __restrict__ Fo,
    float*  __restrict__ out_wz,
    float*  __restrict__ out_wf,
    float*  __restrict__ out_bz,
    float*  __restrict__ out_bf)
{
    __shared__ float red[8][2 * ROWS];   // [warp][r*2 + gate]
    __shared__ float coef[3][ROWS];

    const int bh0  = blockIdx.x * ROWS;
    const int b    = bh0 >> 10;
    const int h0   = bh0 & (H_ - 1);
    const int t    = threadIdx.x;
    const int wid  = t >> 5;
    const int lane = t & 31;

    const size_t row0 = (size_t)bh0 << 8;   // float4 offset of first row

    // ---- prefetch stream rows 0,1 (touch-once; overlap with GEMV chain) ----
    float4 zA = __ldcs(Z + row0 + t);
    float4 fA = __ldcs(F + row0 + t);
    float4 zB = __ldcs(Z + row0 + 256 + t);
    float4 fB = __ldcs(F + row0 + 256 + t);

    // ---- epilogue scalar preloads: threads 0..7, one row each ----
    float hp = 0.f, wzs = 0.f, wfs = 0.f, bzs = 0.f, bfs = 0.f;
    float vz = 0.f, vf = 0.f, bsz = 0.f, bsf = 0.f;
    if (t < ROWS) {
        const int bh = bh0 + t;
        const int h  = h0 + t;
        hp  = hidden_prev[bh];
        wzs = wz_state[bh];  wfs = wf_state[bh];
        bzs = bz_state[bh];  bfs = bf_state[bh];
        vz  = wv_z[h];       vf  = wv_f[h];
        bsz = bias_z[h];     bsf = bias_f[h];
    }

    // ---- phase 1: GEMV partials (x + wm rows, L2-hot) ----
    const float4 xv = __ldg(x4 + ((size_t)b << 8) + t);
    float pz[ROWS], pf[ROWS];
    #pragma unroll
    for (int r = 0; r < ROWS; ++r) {
        const float4 wzv = __ldg(wmz4 + ((size_t)(h0 + r) << 8) + t);
        const float4 wfv = __ldg(wmf4 + ((size_t)(h0 + r) << 8) + t);
        pz[r] = xv.x * wzv.x + xv.y * wzv.y + xv.z * wzv.z + xv.w * wzv.w;
        pf[r] = xv.x * wfv.x + xv.y * wfv.y + xv.z * wfv.z + xv.w * wfv.w;
    }
    #pragma unroll
    for (int o = 16; o > 0; o >>= 1) {
        #pragma unroll
        for (int r = 0; r < ROWS; ++r) {
            pz[r] += __shfl_xor_sync(0xffffffffu, pz[r], o);
            pf[r] += __shfl_xor_sync(0xffffffffu, pf[r], o);
        }
    }
    if (lane == 0) {
        #pragma unroll
        for (int r = 0; r < ROWS; ++r) {
            red[wid][r * 2]     = pz[r];
            red[wid][r * 2 + 1] = pf[r];
        }
    }
    __syncthreads();

    // ---- epilogue: threads 0..7 in parallel, operands already in regs ----
    if (t < ROWS) {
        float AZ = 0.f, AF = 0.f;
        #pragma unroll
        for (int w = 0; w < 8; ++w) {
            AZ += red[w][t * 2];
            AF += red[w][t * 2 + 1];
        }

        const int bh = bh0 + t;
        const float z    = tanhf(AZ + vz * hp + bsz);
        const float fpre = AF + vf * hp + bsf;
        const float f    = 1.f / (1.f + expf(-fpre));

        const float zf = (1.f - f) * (1.f - z * z);
        const float fz = (hp - z) * (1.f - f) * f;
        const float common = f + zf * vz + fz * vf;

        out_cell[bh] = hp * f + (1.f - f) * z;
        out_wz[bh]   = hp * zf + common * wzs;
        out_wf[bh]   = hp * fz + common * wfs;
        out_bz[bh]   = zf + common * bzs;
        out_bf[bh]   = fz + common * bfs;

        coef[0][t] = common;
        coef[1][t] = zf;
        coef[2][t] = fz;
    }
    __syncthreads();

    // ---- phase 2: pipelined stream: compute row r, prefetch row r+2 ----
    #pragma unroll
    for (int r = 0; r < ROWS; ++r) {
        const float4 zc = zA, fc = fA;
        zA = zB; fA = fB;
        if (r + 2 < ROWS) {
            const size_t nxt = row0 + (size_t)((r + 2) << 8) + t;
            zB = __ldcs(Z + nxt);
            fB = __ldcs(F + nxt);
        }

        const float c   = coef[0][r];
        const float czf = coef[1][r];
        const float cfz = coef[2][r];

        float4 zo, fo;
        zo.x = c * zc.x + czf * xv.x;
        zo.y = c * zc.y + czf * xv.y;
        zo.z = c * zc.z + czf * xv.z;
        zo.w = c * zc.w + czf * xv.w;
        fo.x = c * fc.x + cfz * xv.x;
        fo.y = c * fc.y + cfz * xv.y;
        fo.z = c * fc.z + cfz * xv.z;
        fo.w = c * fc.w + cfz * xv.w;

        const size_t off = row0 + (size_t)(r << 8) + t;
        __stcs(Zo + off, zo);
        __stcs(Fo + off, fo);
    }
}

// ---------------------------------------------------------------------------
extern "C" void kernel_launch(void* const* d_in, const int* in_sizes, int n_in,
                              void* d_out, int out_size)
{
    const float* x           = (const float*)d_in[0];
    const float* hidden_prev = (const float*)d_in[1];
    const float* Z_state     = (const float*)d_in[2];
    const float* F_state     = (const float*)d_in[3];
    const float* wz_state    = (const float*)d_in[4];
    const float* wf_state    = (const float*)d_in[5];
    const float* bz_state    = (const float*)d_in[6];
    const float* bf_state    = (const float*)d_in[7];
    const float* wm_z        = (const float*)d_in[8];
    const float* wm_f        = (const float*)d_in[9];
    const float* wv_z        = (const float*)d_in[10];
    const float* wv_f        = (const float*)d_in[11];
    const float* bias_z      = (const float*)d_in[12];
    const float* bias_f      = (const float*)d_in[13];

    float* out = (float*)d_out;
    // Output tuple layout: new_cell, Z_new, F_new, wz_new, wf_new, bz_new, bf_new
    float* o_cell = out;
    float* o_Z    = out + BH;
    float* o_F    = o_Z + BHI;
    float* o_wz   = o_F + BHI;
    float* o_wf   = o_wz + BH;
    float* o_bz   = o_wf + BH;
    float* o_bf   = o_bz + BH;

    fused_kernel<<<BH / ROWS, 256>>>(
        (const float4*)x, hidden_prev,
        (const float4*)Z_state, (const float4*)F_state,
        wz_state, wf_state, bz_state, bf_state,
        (const float4*)wm_z, (const float4*)wm_f,
        wv_z, wv_f, bias_z, bias_f,
        o_cell, (float4*)o_Z, (float4*)o_F,
        o_wz, o_wf, o_bz, o_bf);
}